// round 15
// baseline (speedup 1.0000x reference)
#include <cuda_runtime.h>
#include <cstdint>

#define B_TOTAL 8192
#define H_      200
#define T_      100
#define OUTC    400
#define TILE_B  64
#define NCTA    128
#define NTHREADS 512      // 16 warps: wb in {0..3} (16 batch rows each), wc in {0..3} (n slices)

// ---- __device__ scratch (allocation-free rule) ----
// B fragments, tf32-rounded: L0 (U0 only): 4*25*25 tiles; L1,L2: 4*50*25 tiles. 64 floats/tile.
__device__ float g_bf[12500 * 64];                                    // 3.2 MB
// c-state in C-fragment order: [cta][layer][warp16][ni7][lane32][4]
__device__ float g_cbuf[(size_t)NCTA * 3 * 16 * 7 * 32 * 4];          // 22 MB, L2-resident

typedef unsigned int u32;

__device__ __forceinline__ float tf32f(float v) {
    u32 r; asm("cvt.rna.tf32.f32 %0, %1;" : "=r"(r) : "f"(v));
    return __uint_as_float(r);
}
__device__ __forceinline__ void mma_tf32(float c[4], const uint4& a, float2 b) {
    asm volatile(
        "mma.sync.aligned.m16n8k8.row.col.f32.tf32.tf32.f32 "
        "{%0,%1,%2,%3}, {%4,%5,%6,%7}, {%8,%9}, {%0,%1,%2,%3};"
        : "+f"(c[0]), "+f"(c[1]), "+f"(c[2]), "+f"(c[3])
        : "r"(a.x), "r"(a.y), "r"(a.z), "r"(a.w),
          "r"(__float_as_uint(b.x)), "r"(__float_as_uint(b.y)));
}
__device__ __forceinline__ float sigm_(float x) { return 1.0f / (1.0f + __expf(-x)); }
__device__ __forceinline__ float tanh_(float x) {
    float e = __expf(-2.0f * fabsf(x));
    float r = (1.0f - e) / (1.0f + e);
    return copysignf(r, x);
}

// ---------------- weight reshuffle: row-major [K][800] -> B-fragment order ----------------
// Fragment map (m16n8k8 tf32, B col-major 8x8): b0 at (k=lane&3, n=lane>>2), b1 at (k+4, n).
// Tile order: L0: gate*625 + kt*25 + nt ; L1: 2500 + gate*1250 + kt*25 + nt ; L2: 7500 + ...
__global__ void prep_kernel(const float* __restrict__ U0,
                            const float* __restrict__ W1, const float* __restrict__ U1,
                            const float* __restrict__ W2, const float* __restrict__ U2) {
    int g = blockIdx.x * blockDim.x + threadIdx.x;
    if (g >= 12500 * 32) return;
    int tile = g >> 5, lane = g & 31;
    int gate, kt, nt;
    const float* src;
    int kb;
    if (tile < 2500) {
        int t = tile; gate = t / 625; t %= 625; kt = t / 25; nt = t % 25;
        src = U0; kb = kt * 8;
    } else if (tile < 7500) {
        int t = tile - 2500; gate = t / 1250; t %= 1250; kt = t / 25; nt = t % 25;
        if (kt < 25) { src = W1; kb = kt * 8; } else { src = U1; kb = (kt - 25) * 8; }
    } else {
        int t = tile - 7500; gate = t / 1250; t %= 1250; kt = t / 25; nt = t % 25;
        if (kt < 25) { src = W2; kb = kt * 8; } else { src = U2; kb = (kt - 25) * 8; }
    }
    int n  = nt * 8 + (lane >> 2);
    int kr = lane & 3;
    g_bf[(size_t)tile * 64 + lane * 2]     = tf32f(src[(kb + kr)     * 800 + gate * H_ + n]);
    g_bf[(size_t)tile * 64 + lane * 2 + 1] = tf32f(src[(kb + kr + 4) * 800 + gate * H_ + n]);
}

// ---------------- one gate's GEMM: C[7][4] = bias (+x*W0 for L0) + h @ Wgate ----------------
// A fragments of h live in smem: h[mt(4)][kt(25)][lane(32)][4]; warp wb owns mt=wb (16 rows).
template<int L>
__device__ __forceinline__ void gate_gemm(
    float C[7][4], int gate,
    const float* hprev, const float* hcur,
    const float* __restrict__ bias, const float* __restrict__ W0, const float* xbuf,
    int wb, int ntbase, int cnt, int lane)
{
    constexpr int KT = (L == 0) ? 25 : 50;
    const size_t LOFF = (L == 0) ? 0 : (L == 1) ? (size_t)2500 * 64 : (size_t)7500 * 64;

    float xl = 0.f, xh = 0.f;
    if (L == 0) {
        int r = lane >> 2;
        xl = xbuf[wb * 16 + r];
        xh = xbuf[wb * 16 + 8 + r];
    }
#pragma unroll
    for (int ni = 0; ni < 7; ++ni) {
        if (ni < cnt) {
            int j0 = (ntbase + ni) * 8 + 2 * (lane & 3);
            float b0 = __ldg(bias + gate * H_ + j0), b1 = __ldg(bias + gate * H_ + j0 + 1);
            if (L == 0) {
                float w0 = __ldg(W0 + gate * H_ + j0), w1 = __ldg(W0 + gate * H_ + j0 + 1);
                C[ni][0] = fmaf(xl, w0, b0); C[ni][1] = fmaf(xl, w1, b1);
                C[ni][2] = fmaf(xh, w0, b0); C[ni][3] = fmaf(xh, w1, b1);
            } else {
                C[ni][0] = b0; C[ni][1] = b1; C[ni][2] = b0; C[ni][3] = b1;
            }
        }
    }
    const float* bf = g_bf + LOFF + ((size_t)(gate * KT) * 25 + ntbase) * 64 + lane * 2;

    // pass 1: K[0:200) against (L0 ? hcur : hprev)
    {
        const float* hA = (L == 0) ? hcur : hprev;
#pragma unroll 5
        for (int kt = 0; kt < 25; ++kt) {
            uint4 a0 = *(const uint4*)(hA + ((wb * 25 + kt) * 32 + lane) * 4);
            const float* bk = bf + (size_t)kt * 25 * 64;
#pragma unroll
            for (int ni = 0; ni < 7; ++ni) {
                if (ni < cnt) {
                    float2 bv = *(const float2*)(bk + ni * 64);
                    mma_tf32(C[ni], a0, bv);
                }
            }
        }
    }
    // pass 2 (L>0): K[200:400) against hcur (recurrent U part)
    if (L > 0) {
#pragma unroll 5
        for (int kt = 0; kt < 25; ++kt) {
            uint4 a0 = *(const uint4*)(hcur + ((wb * 25 + kt) * 32 + lane) * 4);
            const float* bk = bf + (size_t)(25 + kt) * 25 * 64;
#pragma unroll
            for (int ni = 0; ni < 7; ++ni) {
                if (ni < cnt) {
                    float2 bv = *(const float2*)(bk + ni * 64);
                    mma_tf32(C[ni], a0, bv);
                }
            }
        }
    }
}

template<int L>
__device__ __forceinline__ void do_layer(
    const float* hprev, float* hcur, const float* xbuf,
    const float* __restrict__ bias, const float* __restrict__ W0,
    float* __restrict__ cb, int t, int wb, int ntbase, int cnt, int lane)
{
    float si[7][4], cn[7][4], C[7][4];
    // i gate
    gate_gemm<L>(C, 0, hprev, hcur, bias, W0, xbuf, wb, ntbase, cnt, lane);
#pragma unroll
    for (int ni = 0; ni < 7; ++ni) if (ni < cnt)
#pragma unroll
        for (int q = 0; q < 4; ++q) si[ni][q] = sigm_(C[ni][q]);
    // f gate -> cn = sigmoid(f) * c_old
    gate_gemm<L>(C, 1, hprev, hcur, bias, W0, xbuf, wb, ntbase, cnt, lane);
#pragma unroll
    for (int ni = 0; ni < 7; ++ni) if (ni < cnt) {
        float4 c4 = make_float4(0.f, 0.f, 0.f, 0.f);
        if (t > 0) c4 = *(const float4*)(cb + (ni * 32 + lane) * 4);
        cn[ni][0] = sigm_(C[ni][0]) * c4.x;
        cn[ni][1] = sigm_(C[ni][1]) * c4.y;
        cn[ni][2] = sigm_(C[ni][2]) * c4.z;
        cn[ni][3] = sigm_(C[ni][3]) * c4.w;
    }
    // g gate -> cn += si * tanh(g); persist c
    gate_gemm<L>(C, 2, hprev, hcur, bias, W0, xbuf, wb, ntbase, cnt, lane);
#pragma unroll
    for (int ni = 0; ni < 7; ++ni) if (ni < cnt) {
#pragma unroll
        for (int q = 0; q < 4; ++q) cn[ni][q] = fmaf(si[ni][q], tanh_(C[ni][q]), cn[ni][q]);
        *(float4*)(cb + (ni * 32 + lane) * 4) =
            make_float4(cn[ni][0], cn[ni][1], cn[ni][2], cn[ni][3]);
    }
    // o gate -> h = sigmoid(o) * tanh(cn)
    gate_gemm<L>(C, 3, hprev, hcur, bias, W0, xbuf, wb, ntbase, cnt, lane);
#pragma unroll
    for (int ni = 0; ni < 7; ++ni) if (ni < cnt)
#pragma unroll
        for (int q = 0; q < 4; ++q) C[ni][q] = sigm_(C[ni][q]) * tanh_(cn[ni][q]);

    __syncthreads();   // all warps done reading old hcur fragments
    // write new h directly into A-fragment layout, tf32-rounded.
    // C elem (m,j): c0:(r, j0) c1:(r, j0+1) c2:(r+8, j0) c3:(r+8, j0+1), r=lane>>2, j0=nt*8+2*(lane&3)
    // A slot for (m,k): lane=(m%8)*4+(k&3), reg=(k&4?2:0)+(m>=8?1:0)
#pragma unroll
    for (int ni = 0; ni < 7; ++ni) if (ni < cnt) {
        int nt = ntbase + ni;
        int j0 = nt * 8 + 2 * (lane & 3);
        int r0 = (j0 & 4) ? 2 : 0;
        int l0 = ((lane >> 2) << 2) + (j0 & 3);
        float* base = hcur + ((wb * 25 + nt) * 32) * 4;
        *(float2*)(base + l0 * 4 + r0)       = make_float2(tf32f(C[ni][0]), tf32f(C[ni][2]));
        *(float2*)(base + (l0 + 1) * 4 + r0) = make_float2(tf32f(C[ni][1]), tf32f(C[ni][3]));
    }
    __syncthreads();   // new h visible to all warps
}

__global__ void __launch_bounds__(NTHREADS, 1) lstm_mma_kernel(
    const float* __restrict__ x,  const float* __restrict__ W0,
    const float* __restrict__ b0v, const float* __restrict__ b1v, const float* __restrict__ b2v,
    const float* __restrict__ Wfc, const float* __restrict__ bfc,
    float* __restrict__ out)
{
    extern __shared__ float sm[];
    float* hs0  = sm;            // [4 mt][25 kt][32][4] fragment layout, 12800 fl
    float* hs1  = sm + 12800;
    float* hs2  = sm + 25600;
    float* xbuf = sm + 38400;    // [64]

    const int tid = threadIdx.x, lane = tid & 31, wid = tid >> 5;
    const int wb = wid >> 2, wc = wid & 3;      // wb: m-tile (16 rows); wc: n slice
    const int ntbase = (wc == 0) ? 0 : 1 + wc * 6;   // 0,7,13,19
    const int cnt    = (wc == 0) ? 7 : 6;
    const int bbase  = blockIdx.x * TILE_B;

    for (int i = tid; i < 3 * 12800; i += NTHREADS) sm[i] = 0.f;
    __syncthreads();

    float* cb0 = g_cbuf + (((size_t)blockIdx.x * 3 + 0) * 16 + wid) * 896;
    float* cb1 = g_cbuf + (((size_t)blockIdx.x * 3 + 1) * 16 + wid) * 896;
    float* cb2 = g_cbuf + (((size_t)blockIdx.x * 3 + 2) * 16 + wid) * 896;

    for (int t = 0; t < T_; ++t) {
        if (tid < TILE_B) xbuf[tid] = x[(size_t)(bbase + tid) * T_ + t];
        __syncthreads();
        do_layer<0>(nullptr, hs0, xbuf, b0v, W0, cb0, t, wb, ntbase, cnt, lane);
        do_layer<1>(hs0,     hs1, xbuf, b1v, W0, cb1, t, wb, ntbase, cnt, lane);
        do_layer<2>(hs1,     hs2, xbuf, b2v, W0, cb2, t, wb, ntbase, cnt, lane);
    }

    // ---- reconstruct plain h2 [k][64] into hs0 (hs0 no longer needed) ----
    for (int idx = tid; idx < 4 * 25 * 32; idx += NTHREADS) {
        int tile = idx >> 5, ln = idx & 31;
        int mt = tile / 25, kt = tile % 25;
        float4 v = *(const float4*)(hs2 + (tile * 32 + ln) * 4);
        int m = mt * 16 + (ln >> 2), k = kt * 8 + (ln & 3);
        hs0[k * 64 + m]           = v.x;   // reg0: (m,   k)
        hs0[k * 64 + m + 8]       = v.y;   // reg1: (m+8, k)
        hs0[(k + 4) * 64 + m]     = v.z;   // reg2: (m,   k+4)
        hs0[(k + 4) * 64 + m + 8] = v.w;   // reg3: (m+8, k+4)
    }
    __syncthreads();

    // ---- dense head: y[b][m] = tanh(h2[b] @ Wfc[:,m] + bfc[m]) ----
    const int b = tid & 63, seg = tid >> 6;   // 8 segments of 50 columns
    for (int m0 = seg * 50; m0 < seg * 50 + 50; m0 += 2) {
        float2 acc = *(const float2*)(bfc + m0);
#pragma unroll 4
        for (int k = 0; k < H_; ++k) {
            float h = hs0[k * 64 + b];
            float2 w = *(const float2*)(Wfc + k * OUTC + m0);
            acc.x = fmaf(h, w.x, acc.x);
            acc.y = fmaf(h, w.y, acc.y);
        }
        out[(size_t)(bbase + b) * OUTC + m0]     = tanh_(acc.x);
        out[(size_t)(bbase + b) * OUTC + m0 + 1] = tanh_(acc.y);
    }
}

extern "C" void kernel_launch(void* const* d_in, const int* in_sizes, int n_in,
                              void* d_out, int out_size) {
    (void)in_sizes; (void)n_in; (void)out_size;
    const float* x   = (const float*)d_in[0];
    const float* W0  = (const float*)d_in[1];
    const float* U0  = (const float*)d_in[2];
    const float* b0v = (const float*)d_in[3];
    const float* W1  = (const float*)d_in[4];
    const float* U1  = (const float*)d_in[5];
    const float* b1v = (const float*)d_in[6];
    const float* W2  = (const float*)d_in[7];
    const float* U2  = (const float*)d_in[8];
    const float* b2v = (const float*)d_in[9];
    const float* Wfc = (const float*)d_in[10];
    const float* bfc = (const float*)d_in[11];
    float* out = (float*)d_out;

    prep_kernel<<<(12500 * 32 + 255) / 256, 256>>>(U0, W1, U1, W2, U2);

    const int smem_bytes = (3 * 12800 + TILE_B) * (int)sizeof(float);   // 153,856 B
    cudaFuncSetAttribute(lstm_mma_kernel, cudaFuncAttributeMaxDynamicSharedMemorySize, smem_bytes);
    lstm_mma_kernel<<<NCTA, NTHREADS, smem_bytes>>>(
        x, W0, b0v, b1v, b2v, Wfc, bfc, out);
}

// round 16
// speedup vs baseline: 1.3220x; 1.3220x over previous
#include <cuda_runtime.h>
#include <cstdint>

#define B_TOTAL 8192
#define H_      200
#define T_      100
#define OUTC    400
#define TILE_B  64
#define NCTA    128
#define NTHREADS 384      // 12 warps: wb in {0,1} (32 batch rows), wc in {0..5} (n slices)

// ---- __device__ scratch (allocation-free rule) ----
// B fragments, tf32-rounded: L0 (U0 only): 4*25*25 tiles; L1,L2: 4*50*25 tiles. 64 floats/tile.
__device__ float g_bf[12500 * 64];                                    // 3.2 MB
// c-state in C-fragment order: [cta][layer][warp12][mi2][ni5][lane32][4]
__device__ float g_cbuf[(size_t)NCTA * 3 * 12 * 2 * 5 * 32 * 4];      // 23.6 MB, L2-resident

typedef unsigned int u32;

__device__ __forceinline__ float tf32f(float v) {
    u32 r; asm("cvt.rna.tf32.f32 %0, %1;" : "=r"(r) : "f"(v));
    return __uint_as_float(r);
}
__device__ __forceinline__ void mma_tf32(float c[4], const uint4& a, float2 b) {
    asm volatile(
        "mma.sync.aligned.m16n8k8.row.col.f32.tf32.tf32.f32 "
        "{%0,%1,%2,%3}, {%4,%5,%6,%7}, {%8,%9}, {%0,%1,%2,%3};"
        : "+f"(c[0]), "+f"(c[1]), "+f"(c[2]), "+f"(c[3])
        : "r"(a.x), "r"(a.y), "r"(a.z), "r"(a.w),
          "r"(__float_as_uint(b.x)), "r"(__float_as_uint(b.y)));
}
__device__ __forceinline__ float sigm_(float x) { return 1.0f / (1.0f + __expf(-x)); }
__device__ __forceinline__ float tanh_(float x) {
    float e = __expf(-2.0f * fabsf(x));
    float r = (1.0f - e) / (1.0f + e);
    return copysignf(r, x);
}

// ---------------- weight reshuffle: row-major [K][800] -> B-fragment order ----------------
// Fragment map (m16n8k8 tf32, B col-major 8x8): b0 at (k=lane&3, n=lane>>2), b1 at (k+4, n).
// Tile order: L0: gate*625 + kt*25 + nt ; L1: 2500 + gate*1250 + kt*25 + nt ; L2: 7500 + ...
__global__ void prep_kernel(const float* __restrict__ U0,
                            const float* __restrict__ W1, const float* __restrict__ U1,
                            const float* __restrict__ W2, const float* __restrict__ U2) {
    int g = blockIdx.x * blockDim.x + threadIdx.x;
    if (g >= 12500 * 32) return;
    int tile = g >> 5, lane = g & 31;
    int gate, kt, nt;
    const float* src;
    int kb;
    if (tile < 2500) {
        int t = tile; gate = t / 625; t %= 625; kt = t / 25; nt = t % 25;
        src = U0; kb = kt * 8;
    } else if (tile < 7500) {
        int t = tile - 2500; gate = t / 1250; t %= 1250; kt = t / 25; nt = t % 25;
        if (kt < 25) { src = W1; kb = kt * 8; } else { src = U1; kb = (kt - 25) * 8; }
    } else {
        int t = tile - 7500; gate = t / 1250; t %= 1250; kt = t / 25; nt = t % 25;
        if (kt < 25) { src = W2; kb = kt * 8; } else { src = U2; kb = (kt - 25) * 8; }
    }
    int n  = nt * 8 + (lane >> 2);
    int kr = lane & 3;
    g_bf[(size_t)tile * 64 + lane * 2]     = tf32f(src[(kb + kr)     * 800 + gate * H_ + n]);
    g_bf[(size_t)tile * 64 + lane * 2 + 1] = tf32f(src[(kb + kr + 4) * 800 + gate * H_ + n]);
}

// ---------------- one gate's GEMM: C[2][5][4] = bias (+x*W0 for L0) + h @ Wgate ----------------
// A fragments of h live in smem: h[mt(4)][kt(25)][lane(32)][4]; warp wb owns mt {2wb, 2wb+1}.
template<int L>
__device__ __forceinline__ void gate_gemm(
    float C[2][5][4], int gate,
    const float* hprev, const float* hcur,
    const float* __restrict__ bias, const float* __restrict__ W0, const float* xbuf,
    int wb, int ntbase, int cnt, int lane)
{
    constexpr int KT = (L == 0) ? 25 : 50;
    const size_t LOFF = (L == 0) ? 0 : (L == 1) ? (size_t)2500 * 64 : (size_t)7500 * 64;

    float xl0 = 0.f, xh0 = 0.f, xl1 = 0.f, xh1 = 0.f;
    if (L == 0) {
        int r = lane >> 2;
        xl0 = xbuf[wb * 32 + r];      xh0 = xbuf[wb * 32 + r + 8];
        xl1 = xbuf[wb * 32 + 16 + r]; xh1 = xbuf[wb * 32 + 24 + r];
    }
#pragma unroll
    for (int ni = 0; ni < 5; ++ni) {
        if (ni < cnt) {
            int j0 = (ntbase + ni) * 8 + 2 * (lane & 3);
            float b0 = __ldg(bias + gate * H_ + j0), b1 = __ldg(bias + gate * H_ + j0 + 1);
            if (L == 0) {
                float w0 = __ldg(W0 + gate * H_ + j0), w1 = __ldg(W0 + gate * H_ + j0 + 1);
                C[0][ni][0] = fmaf(xl0, w0, b0); C[0][ni][1] = fmaf(xl0, w1, b1);
                C[0][ni][2] = fmaf(xh0, w0, b0); C[0][ni][3] = fmaf(xh0, w1, b1);
                C[1][ni][0] = fmaf(xl1, w0, b0); C[1][ni][1] = fmaf(xl1, w1, b1);
                C[1][ni][2] = fmaf(xh1, w0, b0); C[1][ni][3] = fmaf(xh1, w1, b1);
            } else {
                C[0][ni][0] = b0; C[0][ni][1] = b1; C[0][ni][2] = b0; C[0][ni][3] = b1;
                C[1][ni][0] = b0; C[1][ni][1] = b1; C[1][ni][2] = b0; C[1][ni][3] = b1;
            }
        }
    }
    const float* bf = g_bf + LOFF + ((size_t)(gate * KT) * 25 + ntbase) * 64 + lane * 2;
    const int mt0 = wb * 2;

    // pass 1: K[0:200) against (L0 ? hcur : hprev)
    {
        const float* hA = (L == 0) ? hcur : hprev;
#pragma unroll 5
        for (int kt = 0; kt < 25; ++kt) {
            uint4 a0 = *(const uint4*)(hA + (((mt0    ) * 25 + kt) * 32 + lane) * 4);
            uint4 a1 = *(const uint4*)(hA + (((mt0 + 1) * 25 + kt) * 32 + lane) * 4);
            const float* bk = bf + (size_t)kt * 25 * 64;
#pragma unroll
            for (int ni = 0; ni < 5; ++ni) {
                if (ni < cnt) {
                    float2 bv = *(const float2*)(bk + ni * 64);
                    mma_tf32(C[0][ni], a0, bv);
                    mma_tf32(C[1][ni], a1, bv);
                }
            }
        }
    }
    // pass 2 (L>0): K[200:400) against hcur (recurrent U part)
    if (L > 0) {
#pragma unroll 5
        for (int kt = 0; kt < 25; ++kt) {
            uint4 a0 = *(const uint4*)(hcur + (((mt0    ) * 25 + kt) * 32 + lane) * 4);
            uint4 a1 = *(const uint4*)(hcur + (((mt0 + 1) * 25 + kt) * 32 + lane) * 4);
            const float* bk = bf + (size_t)(25 + kt) * 25 * 64;
#pragma unroll
            for (int ni = 0; ni < 5; ++ni) {
                if (ni < cnt) {
                    float2 bv = *(const float2*)(bk + ni * 64);
                    mma_tf32(C[0][ni], a0, bv);
                    mma_tf32(C[1][ni], a1, bv);
                }
            }
        }
    }
}

// Gate order i -> g -> f -> o with one carry array S:
//   i: S = sigm(z)           g: S *= tanh(z)
//   f: S = sigm(z)*c_old + S   (this is c_new; persist)
//   o: h = sigm(z)*tanh(S)
template<int L>
__device__ __forceinline__ void do_layer(
    const float* hprev, float* hcur, const float* xbuf,
    const float* __restrict__ bias, const float* __restrict__ W0,
    float* __restrict__ cb, int t, int wb, int ntbase, int cnt, int lane)
{
    float S[2][5][4], C[2][5][4];
    // i gate
    gate_gemm<L>(C, 0, hprev, hcur, bias, W0, xbuf, wb, ntbase, cnt, lane);
#pragma unroll
    for (int mi = 0; mi < 2; ++mi)
#pragma unroll
    for (int ni = 0; ni < 5; ++ni) if (ni < cnt)
#pragma unroll
        for (int q = 0; q < 4; ++q) S[mi][ni][q] = sigm_(C[mi][ni][q]);
    // g gate: S = sigm(i)*tanh(g)
    gate_gemm<L>(C, 2, hprev, hcur, bias, W0, xbuf, wb, ntbase, cnt, lane);
#pragma unroll
    for (int mi = 0; mi < 2; ++mi)
#pragma unroll
    for (int ni = 0; ni < 5; ++ni) if (ni < cnt)
#pragma unroll
        for (int q = 0; q < 4; ++q) S[mi][ni][q] *= tanh_(C[mi][ni][q]);
    // f gate: S += sigm(f)*c_old  -> c_new; persist
    gate_gemm<L>(C, 1, hprev, hcur, bias, W0, xbuf, wb, ntbase, cnt, lane);
#pragma unroll
    for (int mi = 0; mi < 2; ++mi)
#pragma unroll
    for (int ni = 0; ni < 5; ++ni) if (ni < cnt) {
        float4 c4 = make_float4(0.f, 0.f, 0.f, 0.f);
        if (t > 0) c4 = *(const float4*)(cb + ((mi * 5 + ni) * 32 + lane) * 4);
        S[mi][ni][0] = fmaf(sigm_(C[mi][ni][0]), c4.x, S[mi][ni][0]);
        S[mi][ni][1] = fmaf(sigm_(C[mi][ni][1]), c4.y, S[mi][ni][1]);
        S[mi][ni][2] = fmaf(sigm_(C[mi][ni][2]), c4.z, S[mi][ni][2]);
        S[mi][ni][3] = fmaf(sigm_(C[mi][ni][3]), c4.w, S[mi][ni][3]);
        *(float4*)(cb + ((mi * 5 + ni) * 32 + lane) * 4) =
            make_float4(S[mi][ni][0], S[mi][ni][1], S[mi][ni][2], S[mi][ni][3]);
    }
    // o gate: h = sigm(o)*tanh(c_new)
    gate_gemm<L>(C, 3, hprev, hcur, bias, W0, xbuf, wb, ntbase, cnt, lane);
#pragma unroll
    for (int mi = 0; mi < 2; ++mi)
#pragma unroll
    for (int ni = 0; ni < 5; ++ni) if (ni < cnt)
#pragma unroll
        for (int q = 0; q < 4; ++q) C[mi][ni][q] = sigm_(C[mi][ni][q]) * tanh_(S[mi][ni][q]);

    __syncthreads();   // all warps done reading old hcur fragments
    // write new h directly into A-fragment layout, tf32-rounded.
    // C elem (m,j): c0:(r, j0) c1:(r, j0+1) c2:(r+8, j0) c3:(r+8, j0+1), r=lane>>2, j0=nt*8+2*(lane&3)
    // A slot for (m,k): lane=(m%8)*4+(k&3), reg=(k&4?2:0)+(m>=8?1:0)
#pragma unroll
    for (int mi = 0; mi < 2; ++mi)
#pragma unroll
    for (int ni = 0; ni < 5; ++ni) if (ni < cnt) {
        int nt = ntbase + ni;
        int j0 = nt * 8 + 2 * (lane & 3);
        int r0 = (j0 & 4) ? 2 : 0;
        int l0 = ((lane >> 2) << 2) + (j0 & 3);
        float* base = hcur + (((wb * 2 + mi) * 25 + nt) * 32) * 4;
        *(float2*)(base + l0 * 4 + r0)       = make_float2(tf32f(C[mi][ni][0]), tf32f(C[mi][ni][2]));
        *(float2*)(base + (l0 + 1) * 4 + r0) = make_float2(tf32f(C[mi][ni][1]), tf32f(C[mi][ni][3]));
    }
    __syncthreads();   // new h visible to all warps
}

__global__ void __launch_bounds__(NTHREADS, 1) lstm_mma_kernel(
    const float* __restrict__ x,  const float* __restrict__ W0,
    const float* __restrict__ b0v, const float* __restrict__ b1v, const float* __restrict__ b2v,
    const float* __restrict__ Wfc, const float* __restrict__ bfc,
    float* __restrict__ out)
{
    extern __shared__ float sm[];
    float* hs0  = sm;            // [4 mt][25 kt][32][4] fragment layout, 12800 fl
    float* hs1  = sm + 12800;
    float* hs2  = sm + 25600;
    float* xbuf = sm + 38400;    // [64]

    const int tid = threadIdx.x, lane = tid & 31, wid = tid >> 5;
    const int wb = wid / 6, wc = wid % 6;            // wb: 2 m-tiles; wc: n slice
    const int ntbase = (wc == 0) ? 0 : 5 + 4 * (wc - 1);   // 0,5,9,13,17,21
    const int cnt    = (wc == 0) ? 5 : 4;
    const int bbase  = blockIdx.x * TILE_B;

    for (int i = tid; i < 3 * 12800; i += NTHREADS) sm[i] = 0.f;
    __syncthreads();

    float* cb0 = g_cbuf + (((size_t)blockIdx.x * 3 + 0) * 12 + wid) * 1280;
    float* cb1 = g_cbuf + (((size_t)blockIdx.x * 3 + 1) * 12 + wid) * 1280;
    float* cb2 = g_cbuf + (((size_t)blockIdx.x * 3 + 2) * 12 + wid) * 1280;

    for (int t = 0; t < T_; ++t) {
        if (tid < TILE_B) xbuf[tid] = x[(size_t)(bbase + tid) * T_ + t];
        __syncthreads();
        do_layer<0>(nullptr, hs0, xbuf, b0v, W0, cb0, t, wb, ntbase, cnt, lane);
        do_layer<1>(hs0,     hs1, xbuf, b1v, W0, cb1, t, wb, ntbase, cnt, lane);
        do_layer<2>(hs1,     hs2, xbuf, b2v, W0, cb2, t, wb, ntbase, cnt, lane);
    }

    // ---- reconstruct plain h2 [k][64] into hs0 (hs0 no longer needed) ----
    for (int idx = tid; idx < 4 * 25 * 32; idx += NTHREADS) {
        int tile = idx >> 5, ln = idx & 31;
        int mt = tile / 25, kt = tile % 25;
        float4 v = *(const float4*)(hs2 + (tile * 32 + ln) * 4);
        int m = mt * 16 + (ln >> 2), k = kt * 8 + (ln & 3);
        hs0[k * 64 + m]           = v.x;   // reg0: (m,   k)
        hs0[k * 64 + m + 8]       = v.y;   // reg1: (m+8, k)
        hs0[(k + 4) * 64 + m]     = v.z;   // reg2: (m,   k+4)
        hs0[(k + 4) * 64 + m + 8] = v.w;   // reg3: (m+8, k+4)
    }
    __syncthreads();

    // ---- dense head: y[b][m] = tanh(h2[b] @ Wfc[:,m] + bfc[m]) ----
    const int b = tid / 6, seg = tid % 6;    // 64 b x 6 column groups
    for (int mg = seg; mg < 100; mg += 6) {
        const int m0 = mg * 4;
        float4 acc = *(const float4*)(bfc + m0);
#pragma unroll 4
        for (int k = 0; k < H_; ++k) {
            float h = hs0[k * 64 + b];
            float4 w = *(const float4*)(Wfc + k * OUTC + m0);
            acc.x = fmaf(h, w.x, acc.x); acc.y = fmaf(h, w.y, acc.y);
            acc.z = fmaf(h, w.z, acc.z); acc.w = fmaf(h, w.w, acc.w);
        }
        *(float4*)(out + (size_t)(bbase + b) * OUTC + m0) =
            make_float4(tanh_(acc.x), tanh_(acc.y), tanh_(acc.z), tanh_(acc.w));
    }
}

extern "C" void kernel_launch(void* const* d_in, const int* in_sizes, int n_in,
                              void* d_out, int out_size) {
    (void)in_sizes; (void)n_in; (void)out_size;
    const float* x   = (const float*)d_in[0];
    const float* W0  = (const float*)d_in[1];
    const float* U0  = (const float*)d_in[2];
    const float* b0v = (const float*)d_in[3];
    const float* W1  = (const float*)d_in[4];
    const float* U1  = (const float*)d_in[5];
    const float* b1v = (const float*)d_in[6];
    const float* W2  = (const float*)d_in[7];
    const float* U2  = (const float*)d_in[8];
    const float* b2v = (const float*)d_in[9];
    const float* Wfc = (const float*)d_in[10];
    const float* bfc = (const float*)d_in[11];
    float* out = (float*)d_out;

    prep_kernel<<<(12500 * 32 + 255) / 256, 256>>>(U0, W1, U1, W2, U2);

    const int smem_bytes = (3 * 12800 + TILE_B) * (int)sizeof(float);   // 153,856 B
    cudaFuncSetAttribute(lstm_mma_kernel, cudaFuncAttributeMaxDynamicSharedMemorySize, smem_bytes);
    lstm_mma_kernel<<<NCTA, NTHREADS, smem_bytes>>>(
        x, W0, b0v, b1v, b2v, Wfc, bfc, out);
}